// round 1
// baseline (speedup 1.0000x reference)
#include <cuda_runtime.h>
#include <math.h>

#define NN 100000
#define EE 800000
#define HID 128
#define NH 4
#define DH 32

// ---------------- scratch (static device globals; no allocation) ----------------
__device__ float g_e [(size_t)EE * HID];   // silu(edge_attr @ Wp + bp)   409.6 MB
__device__ float g_ee[(size_t)EE * HID];   // e @ We (per layer)          409.6 MB
__device__ float g_xl[NN * HID];           // source projection
__device__ float g_xr[NN * HID];           // target projection
__device__ float g_h [NN * HID];           // hidden state
__device__ float g_score[EE * NH];         // per-edge per-head scores
__device__ int   g_deg[NN];
__device__ int   g_cursor[NN];
__device__ int   g_rowptr[NN + 1];
__device__ int   g_eids[EE];

// ---------------- edge feature projection: e = silu(attr @ Wp + bp) ----------------
__global__ void eproj_kernel(const float* __restrict__ attr,
                             const float* __restrict__ W,
                             const float* __restrict__ b) {
    int idx = blockIdx.x * blockDim.x + threadIdx.x;   // E*128 threads
    int e = idx >> 7, j = idx & 127;
    float a0 = __ldg(&attr[e * 3 + 0]);
    float a1 = __ldg(&attr[e * 3 + 1]);
    float a2 = __ldg(&attr[e * 3 + 2]);
    float z = __ldg(&b[j]);
    z = fmaf(a0, __ldg(&W[j]),           z);
    z = fmaf(a1, __ldg(&W[HID + j]),     z);
    z = fmaf(a2, __ldg(&W[2 * HID + j]), z);
    g_e[(size_t)idx] = z / (1.0f + expf(-z));          // silu
}

// ---------------- CSR build (by dst) ----------------
__global__ void zero_kernel() {
    int i = blockIdx.x * blockDim.x + threadIdx.x;
    if (i < NN) { g_deg[i] = 0; g_cursor[i] = 0; }
}

__global__ void hist_kernel(const int* __restrict__ ei) {
    int e = blockIdx.x * blockDim.x + threadIdx.x;
    if (e < EE) atomicAdd(&g_deg[ei[EE + e]], 1);
}

__global__ void scan_kernel() {   // single block, 1024 threads, sequential chunks
    __shared__ int sh[1024];
    int tid = threadIdx.x;
    int carry = 0;
    if (tid == 0) g_rowptr[0] = 0;
    for (int base = 0; base < NN; base += 1024) {
        int v = (base + tid < NN) ? g_deg[base + tid] : 0;
        sh[tid] = v;
        __syncthreads();
        for (int off = 1; off < 1024; off <<= 1) {
            int t = (tid >= off) ? sh[tid - off] : 0;
            __syncthreads();
            sh[tid] += t;
            __syncthreads();
        }
        if (base + tid < NN) g_rowptr[base + tid + 1] = sh[tid] + carry;
        int tot = sh[1023];
        __syncthreads();
        carry += tot;
    }
}

__global__ void scatter_kernel(const int* __restrict__ ei) {
    int e = blockIdx.x * blockDim.x + threadIdx.x;
    if (e < EE) {
        int d = ei[EE + e];
        int pos = atomicAdd(&g_cursor[d], 1);
        g_eids[g_rowptr[d] + pos] = e;
    }
}

// ---------------- generic C[M,128] = A[M,128] @ W[128,128] (+bias) ----------------
// MODE 0: g_e -> g_ee      MODE 1: g_h -> g_xl      MODE 2: g_h -> g_xr
template <int MODE>
__global__ __launch_bounds__(256, 2) void gemm_k128(const float* __restrict__ W,
                                                    const float* __restrict__ bias,
                                                    int M) {
    const float* A = (MODE == 0) ? g_e : g_h;
    float* C = (MODE == 0) ? g_ee : ((MODE == 1) ? g_xl : g_xr);

    __shared__ __align__(16) float As[32][132];   // transposed: As[k][m], padded
    __shared__ __align__(16) float Ws[32][HID];   // Ws[k][n]

    int tid = threadIdx.x;
    int tx = tid & 15;          // col group -> cols tx*8 .. tx*8+7
    int ty = tid >> 4;          // row group -> rows ty*8 .. ty*8+7
    int m0 = blockIdx.x * 128;

    float acc[8][8];
#pragma unroll
    for (int i = 0; i < 8; i++)
#pragma unroll
        for (int j = 0; j < 8; j++) acc[i][j] = 0.f;

    int lr = tid >> 3;            // 0..31
    int lc = (tid & 7) << 2;      // 0,4,..,28
    int wk = tid >> 3;            // 0..31
    int wc = (tid & 7) << 4;      // 0,16,..,112

    for (int k0 = 0; k0 < HID; k0 += 32) {
        // A chunk 128x32 -> transposed smem
#pragma unroll
        for (int i = 0; i < 4; i++) {
            int m = m0 + lr + 32 * i;
            float4 v = make_float4(0.f, 0.f, 0.f, 0.f);
            if (m < M) v = *(const float4*)&A[(size_t)m * HID + k0 + lc];
            As[lc + 0][lr + 32 * i] = v.x;
            As[lc + 1][lr + 32 * i] = v.y;
            As[lc + 2][lr + 32 * i] = v.z;
            As[lc + 3][lr + 32 * i] = v.w;
        }
        // W chunk 32x128
#pragma unroll
        for (int i = 0; i < 4; i++) {
            *(float4*)&Ws[wk][wc + 4 * i] =
                *(const float4*)&W[(size_t)(k0 + wk) * HID + wc + 4 * i];
        }
        __syncthreads();

#pragma unroll 8
        for (int kk = 0; kk < 32; kk++) {
            float4 a0 = *(const float4*)&As[kk][ty * 8];
            float4 a1 = *(const float4*)&As[kk][ty * 8 + 4];
            float4 b0 = *(const float4*)&Ws[kk][tx * 8];
            float4 b1 = *(const float4*)&Ws[kk][tx * 8 + 4];
            float a[8] = {a0.x, a0.y, a0.z, a0.w, a1.x, a1.y, a1.z, a1.w};
            float b[8] = {b0.x, b0.y, b0.z, b0.w, b1.x, b1.y, b1.z, b1.w};
#pragma unroll
            for (int i = 0; i < 8; i++)
#pragma unroll
                for (int j = 0; j < 8; j++)
                    acc[i][j] = fmaf(a[i], b[j], acc[i][j]);
        }
        __syncthreads();
    }

#pragma unroll
    for (int i = 0; i < 8; i++) {
        int m = m0 + ty * 8 + i;
        if (m < M) {
#pragma unroll
            for (int j = 0; j < 8; j += 4) {
                float4 o;
                o.x = acc[i][j + 0] + (bias ? __ldg(&bias[tx * 8 + j + 0]) : 0.f);
                o.y = acc[i][j + 1] + (bias ? __ldg(&bias[tx * 8 + j + 1]) : 0.f);
                o.z = acc[i][j + 2] + (bias ? __ldg(&bias[tx * 8 + j + 2]) : 0.f);
                o.w = acc[i][j + 3] + (bias ? __ldg(&bias[tx * 8 + j + 3]) : 0.f);
                *(float4*)&C[(size_t)m * HID + tx * 8 + j] = o;
            }
        }
    }
}

// ---------------- layer-0 node projection (K=12) ----------------
__global__ void node_proj12(const float* __restrict__ x,
                            const float* __restrict__ Wl, const float* __restrict__ bl,
                            const float* __restrict__ Wr, const float* __restrict__ br) {
    int idx = blockIdx.x * blockDim.x + threadIdx.x;    // N*128 threads
    int n = idx >> 7, j = idx & 127;
    float a = __ldg(&bl[j]);
    float b = __ldg(&br[j]);
#pragma unroll
    for (int k = 0; k < 12; k++) {
        float xv = __ldg(&x[n * 12 + k]);
        a = fmaf(xv, __ldg(&Wl[k * HID + j]), a);
        b = fmaf(xv, __ldg(&Wr[k * HID + j]), b);
    }
    g_xl[idx] = a;
    g_xr[idx] = b;
}

// ---------------- per-edge attention score (warp per edge) ----------------
__global__ void edge_score_kernel(const int* __restrict__ ei,
                                  const float* __restrict__ att) {
    int e = blockIdx.x * 4 + (threadIdx.x >> 5);
    int lane = threadIdx.x & 31;
    int src = ei[e];
    int dst = ei[EE + e];
    float s[4];
#pragma unroll
    for (int h = 0; h < 4; h++) {
        int j = h * DH + lane;
        float m = g_xl[src * HID + j] + g_xr[dst * HID + j] + g_ee[(size_t)e * HID + j];
        m = (m > 0.f) ? m : 0.2f * m;                    // leaky_relu(0.2)
        float p = m * __ldg(&att[j]);
#pragma unroll
        for (int off = 16; off; off >>= 1) p += __shfl_xor_sync(0xffffffffu, p, off);
        s[h] = p;
    }
    if (lane == 0)
        *(float4*)&g_score[(size_t)e * 4] = make_float4(s[0], s[1], s[2], s[3]);
}

// ---------------- fused per-node: softmax + aggregate + bias + LN + SiLU (+res) ----------------
template <bool RES, bool LAST>
__global__ void node_fused_kernel(const int* __restrict__ ei,
                                  const float* __restrict__ gat_bias,
                                  const float* __restrict__ lng,
                                  const float* __restrict__ lnb,
                                  float* __restrict__ dout) {
    int n = blockIdx.x * 4 + (threadIdx.x >> 5);
    int lane = threadIdx.x & 31;
    if (n >= NN) return;
    int s0 = g_rowptr[n];
    int s1 = g_rowptr[n + 1];

    // pass 1: per-head max (items = (edge,h); lane&3 == head, invariant with stride 32)
    float mx = -3.4e38f;
    for (int p = s0 * 4 + lane; p < s1 * 4; p += 32) {
        int e = g_eids[p >> 2];
        mx = fmaxf(mx, g_score[(size_t)e * 4 + (p & 3)]);
    }
    mx = fmaxf(mx, __shfl_xor_sync(0xffffffffu, mx, 4));
    mx = fmaxf(mx, __shfl_xor_sync(0xffffffffu, mx, 8));
    mx = fmaxf(mx, __shfl_xor_sync(0xffffffffu, mx, 16));

    // pass 2: per-head denominator
    float den = 0.f;
    for (int p = s0 * 4 + lane; p < s1 * 4; p += 32) {
        int e = g_eids[p >> 2];
        den += expf(g_score[(size_t)e * 4 + (p & 3)] - mx);
    }
    den += __shfl_xor_sync(0xffffffffu, den, 4);
    den += __shfl_xor_sync(0xffffffffu, den, 8);
    den += __shfl_xor_sync(0xffffffffu, den, 16);
    float inv = 1.f / (den + 1e-16f);

    // pass 3: aggregate messages (lanes 0..3 hold head 0..3 stats)
    float acc0 = 0.f, acc1 = 0.f, acc2 = 0.f, acc3 = 0.f;
    for (int i = s0; i < s1; i++) {
        int e = g_eids[i];
        int src = ei[e];
        float a = 0.f;
        if (lane < 4) a = expf(g_score[(size_t)e * 4 + lane] - mx) * inv;
        float al0 = __shfl_sync(0xffffffffu, a, 0);
        float al1 = __shfl_sync(0xffffffffu, a, 1);
        float al2 = __shfl_sync(0xffffffffu, a, 2);
        float al3 = __shfl_sync(0xffffffffu, a, 3);
        const float* xl = &g_xl[(size_t)src * HID];
        acc0 = fmaf(xl[0 * DH + lane], al0, acc0);
        acc1 = fmaf(xl[1 * DH + lane], al1, acc1);
        acc2 = fmaf(xl[2 * DH + lane], al2, acc2);
        acc3 = fmaf(xl[3 * DH + lane], al3, acc3);
    }

    float v0 = acc0 + __ldg(&gat_bias[0 * DH + lane]);
    float v1 = acc1 + __ldg(&gat_bias[1 * DH + lane]);
    float v2 = acc2 + __ldg(&gat_bias[2 * DH + lane]);
    float v3 = acc3 + __ldg(&gat_bias[3 * DH + lane]);

    // LayerNorm over the 128-wide row held by this warp
    float sm = v0 + v1 + v2 + v3;
#pragma unroll
    for (int off = 16; off; off >>= 1) sm += __shfl_xor_sync(0xffffffffu, sm, off);
    float mean = sm * (1.f / 128.f);
    float d0 = v0 - mean, d1 = v1 - mean, d2 = v2 - mean, d3 = v3 - mean;
    float sq = d0 * d0 + d1 * d1 + d2 * d2 + d3 * d3;
#pragma unroll
    for (int off = 16; off; off >>= 1) sq += __shfl_xor_sync(0xffffffffu, sq, off);
    float rstd = rsqrtf(sq * (1.f / 128.f) + 1e-5f);

#pragma unroll
    for (int h = 0; h < 4; h++) {
        int j = h * DH + lane;
        float d = (h == 0 ? d0 : h == 1 ? d1 : h == 2 ? d2 : d3);
        float t = fmaf(d * rstd, __ldg(&lng[j]), __ldg(&lnb[j]));
        float sil = t / (1.f + expf(-t));                 // silu
        float o = RES ? (g_h[n * HID + j] + sil) : sil;
        if (LAST) dout[n * HID + j] = o;
        else      g_h[n * HID + j] = o;
    }
}

// ---------------- launch ----------------
extern "C" void kernel_launch(void* const* d_in, const int* in_sizes, int n_in,
                              void* d_out, int out_size) {
    const float* x     = (const float*)d_in[0];
    const int*   ei    = (const int*)  d_in[1];
    const float* eattr = (const float*)d_in[2];
    const float* epw   = (const float*)d_in[3];
    const float* epb   = (const float*)d_in[4];
    const float* l0Wl  = (const float*)d_in[5];
    const float* l0bl  = (const float*)d_in[6];
    const float* l0Wr  = (const float*)d_in[7];
    const float* l0br  = (const float*)d_in[8];
    const float* l0We  = (const float*)d_in[9];
    const float* l0att = (const float*)d_in[10];
    const float* l0bias= (const float*)d_in[11];
    const float* Wl    = (const float*)d_in[12];
    const float* bl    = (const float*)d_in[13];
    const float* Wr    = (const float*)d_in[14];
    const float* br    = (const float*)d_in[15];
    const float* We    = (const float*)d_in[16];
    const float* att   = (const float*)d_in[17];
    const float* bias  = (const float*)d_in[18];
    const float* lng   = (const float*)d_in[19];
    const float* lnb   = (const float*)d_in[20];
    float* out = (float*)d_out;

    // edge features (shared by all layers)
    eproj_kernel<<<(EE * HID) / 256, 256>>>(eattr, epw, epb);

    // CSR by destination (shared by all layers)
    zero_kernel<<<(NN + 255) / 256, 256>>>();
    hist_kernel<<<(EE + 255) / 256, 256>>>(ei);
    scan_kernel<<<1, 1024>>>();
    scatter_kernel<<<(EE + 255) / 256, 256>>>(ei);

    // ---- layer 0 (12 -> 128, no residual) ----
    node_proj12<<<(NN * HID) / 256, 256>>>(x, l0Wl, l0bl, l0Wr, l0br);
    gemm_k128<0><<<EE / 128, 256>>>(l0We, nullptr, EE);
    edge_score_kernel<<<EE / 4, 128>>>(ei, l0att);
    node_fused_kernel<false, false><<<NN / 4, 128>>>(ei, l0bias, lng, lnb, nullptr);

    // ---- layers 1..3 (residual) ----
    for (int i = 0; i < 3; i++) {
        gemm_k128<1><<<(NN + 127) / 128, 256>>>(Wl + i * HID * HID, bl + i * HID, NN);
        gemm_k128<2><<<(NN + 127) / 128, 256>>>(Wr + i * HID * HID, br + i * HID, NN);
        gemm_k128<0><<<EE / 128, 256>>>(We + i * HID * HID, nullptr, EE);
        edge_score_kernel<<<EE / 4, 128>>>(ei, att + i * HID);
        if (i < 2)
            node_fused_kernel<true, false><<<NN / 4, 128>>>(
                ei, bias + i * HID, lng + (i + 1) * HID, lnb + (i + 1) * HID, nullptr);
        else
            node_fused_kernel<true, true><<<NN / 4, 128>>>(
                ei, bias + i * HID, lng + (i + 1) * HID, lnb + (i + 1) * HID, out);
    }
}

// round 2
// speedup vs baseline: 1.1477x; 1.1477x over previous
#include <cuda_runtime.h>
#include <math.h>

#define NN 100000
#define EE 800000
#define HID 128
#define NH 4
#define DH 32
#define NBLK ((NN + 1023) / 1024)   // 98

// ---------------- scratch (static device globals; no allocation) ----------------
__device__ float g_e [(size_t)EE * HID];   // silu(edge_attr @ Wp + bp)
__device__ float g_xl[NN * HID];           // source projection
__device__ float g_xr[NN * HID];           // target projection
__device__ float g_h [NN * HID];           // hidden state
__device__ float g_score[EE * NH];         // per-edge per-head scores
__device__ int   g_deg[NN];
__device__ int   g_cursor[NN];
__device__ int   g_rowptr[NN + 1];
__device__ int   g_eids[EE];
__device__ int   g_bsum[NBLK];
__device__ int   g_boff[NBLK];

// ---------------- packed fp32x2 helpers (sm_103a FFMA2 — only reachable via PTX) ----
__device__ __forceinline__ unsigned long long pack2(float x, float y) {
    unsigned long long r;
    asm("mov.b64 %0, {%1, %2};" : "=l"(r) : "f"(x), "f"(y));
    return r;
}
__device__ __forceinline__ unsigned long long bcast2(float x) {
    unsigned long long r;
    asm("mov.b64 %0, {%1, %1};" : "=l"(r) : "f"(x));
    return r;
}
__device__ __forceinline__ void ffma2(unsigned long long& d,
                                      unsigned long long a, unsigned long long b) {
    asm("fma.rn.f32x2 %0, %1, %2, %0;" : "+l"(d) : "l"(a), "l"(b));
}

// ---------------- edge feature projection: e = silu(attr @ Wp + bp) ----------------
__global__ void eproj_kernel(const float* __restrict__ attr,
                             const float* __restrict__ W,
                             const float* __restrict__ b) {
    int idx = blockIdx.x * blockDim.x + threadIdx.x;   // E*128 threads
    int e = idx >> 7, j = idx & 127;
    float a0 = __ldg(&attr[e * 3 + 0]);
    float a1 = __ldg(&attr[e * 3 + 1]);
    float a2 = __ldg(&attr[e * 3 + 2]);
    float z = __ldg(&b[j]);
    z = fmaf(a0, __ldg(&W[j]),           z);
    z = fmaf(a1, __ldg(&W[HID + j]),     z);
    z = fmaf(a2, __ldg(&W[2 * HID + j]), z);
    g_e[(size_t)idx] = z / (1.0f + expf(-z));          // silu
}

// ---------------- CSR build (by dst) ----------------
__global__ void zero_kernel() {
    int i = blockIdx.x * blockDim.x + threadIdx.x;
    if (i < NN) { g_deg[i] = 0; g_cursor[i] = 0; }
}

__global__ void hist_kernel(const int* __restrict__ ei) {
    int e = blockIdx.x * blockDim.x + threadIdx.x;
    if (e < EE) atomicAdd(&g_deg[ei[EE + e]], 1);
}

__global__ void deg_block_sum() {
    __shared__ int sh[1024];
    int i = blockIdx.x * 1024 + threadIdx.x;
    sh[threadIdx.x] = (i < NN) ? g_deg[i] : 0;
    __syncthreads();
    for (int off = 512; off; off >>= 1) {
        if (threadIdx.x < off) sh[threadIdx.x] += sh[threadIdx.x + off];
        __syncthreads();
    }
    if (threadIdx.x == 0) g_bsum[blockIdx.x] = sh[0];
}

__global__ void bsum_scan() {   // 1 block, 128 threads scans 98 partials
    __shared__ int sh[128];
    int t = threadIdx.x;
    int v = (t < NBLK) ? g_bsum[t] : 0;
    sh[t] = v;
    __syncthreads();
    for (int off = 1; off < 128; off <<= 1) {
        int u = (t >= off) ? sh[t - off] : 0;
        __syncthreads();
        sh[t] += u;
        __syncthreads();
    }
    if (t < NBLK) g_boff[t] = sh[t] - v;   // exclusive
}

__global__ void rowptr_kernel() {
    __shared__ int sh[1024];
    int i = blockIdx.x * 1024 + threadIdx.x;
    int v = (i < NN) ? g_deg[i] : 0;
    sh[threadIdx.x] = v;
    __syncthreads();
    for (int off = 1; off < 1024; off <<= 1) {
        int u = (threadIdx.x >= off) ? sh[threadIdx.x - off] : 0;
        __syncthreads();
        sh[threadIdx.x] += u;
        __syncthreads();
    }
    if (i < NN) g_rowptr[i + 1] = sh[threadIdx.x] + g_boff[blockIdx.x];
    if (i == 0) g_rowptr[0] = 0;
}

__global__ void scatter_kernel(const int* __restrict__ ei) {
    int e = blockIdx.x * blockDim.x + threadIdx.x;
    if (e < EE) {
        int d = ei[EE + e];
        int pos = atomicAdd(&g_cursor[d], 1);
        g_eids[g_rowptr[d] + pos] = e;
    }
}

// ---------------- node GEMM: C[M,128] = g_h @ W + bias (MODE 1 -> xl, 2 -> xr) -----
template <int MODE>
__global__ __launch_bounds__(256, 2) void gemm_node(const float* __restrict__ W,
                                                    const float* __restrict__ bias,
                                                    int M) {
    const float* A = g_h;
    float* C = (MODE == 1) ? g_xl : g_xr;

    __shared__ __align__(16) float As[32][132];   // transposed: As[k][m]
    __shared__ __align__(16) float Ws[32][HID];   // Ws[k][n]

    int tid = threadIdx.x;
    int tx = tid & 15;
    int ty = tid >> 4;
    int m0 = blockIdx.x * 128;

    unsigned long long acc2[8][4];
#pragma unroll
    for (int i = 0; i < 8; i++)
#pragma unroll
        for (int j = 0; j < 4; j++) acc2[i][j] = 0ull;

    int lr = tid >> 3;
    int lc = (tid & 7) << 2;
    int wk = tid >> 3;
    int wc = (tid & 7) << 4;

    for (int k0 = 0; k0 < HID; k0 += 32) {
#pragma unroll
        for (int i = 0; i < 4; i++) {
            int m = m0 + lr + 32 * i;
            float4 v = make_float4(0.f, 0.f, 0.f, 0.f);
            if (m < M) v = *(const float4*)&A[(size_t)m * HID + k0 + lc];
            As[lc + 0][lr + 32 * i] = v.x;
            As[lc + 1][lr + 32 * i] = v.y;
            As[lc + 2][lr + 32 * i] = v.z;
            As[lc + 3][lr + 32 * i] = v.w;
        }
#pragma unroll
        for (int i = 0; i < 4; i++)
            *(float4*)&Ws[wk][wc + 4 * i] =
                *(const float4*)&W[(size_t)(k0 + wk) * HID + wc + 4 * i];
        __syncthreads();

#pragma unroll 8
        for (int kk = 0; kk < 32; kk++) {
            float4 a0 = *(const float4*)&As[kk][ty * 8];
            float4 a1 = *(const float4*)&As[kk][ty * 8 + 4];
            float4 b0 = *(const float4*)&Ws[kk][tx * 8];
            float4 b1 = *(const float4*)&Ws[kk][tx * 8 + 4];
            unsigned long long bp[4] = {pack2(b0.x, b0.y), pack2(b0.z, b0.w),
                                        pack2(b1.x, b1.y), pack2(b1.z, b1.w)};
            float a[8] = {a0.x, a0.y, a0.z, a0.w, a1.x, a1.y, a1.z, a1.w};
#pragma unroll
            for (int i = 0; i < 8; i++) {
                unsigned long long ap = bcast2(a[i]);
#pragma unroll
                for (int j = 0; j < 4; j++) ffma2(acc2[i][j], ap, bp[j]);
            }
        }
        __syncthreads();
    }

#pragma unroll
    for (int i = 0; i < 8; i++) {
        int m = m0 + ty * 8 + i;
        if (m < M) {
#pragma unroll
            for (int jp = 0; jp < 4; jp += 2) {
                float2 p0 = *(float2*)&acc2[i][jp];
                float2 p1 = *(float2*)&acc2[i][jp + 1];
                float4 o;
                int c = tx * 8 + jp * 2;
                o.x = p0.x + __ldg(&bias[c + 0]);
                o.y = p0.y + __ldg(&bias[c + 1]);
                o.z = p1.x + __ldg(&bias[c + 2]);
                o.w = p1.y + __ldg(&bias[c + 3]);
                *(float4*)&C[(size_t)m * HID + c] = o;
            }
        }
    }
}

// ---------------- fused edge GEMM + attention score -------------------------------
// ee = g_e @ We; m = ee + xl[src] + xr[dst]; score[e][h] = sum_d leaky(m)*att[h][d]
// g_ee is never materialized. EE % 128 == 0.
__global__ __launch_bounds__(256, 2) void gemm_edge_score(const float* __restrict__ W,
                                                          const float* __restrict__ att,
                                                          const int* __restrict__ ei) {
    __shared__ __align__(16) float As[32][132];
    __shared__ __align__(16) float Ws[32][HID];
    __shared__ int s_src[128], s_dst[128];

    int tid = threadIdx.x;
    int tx = tid & 15;
    int ty = tid >> 4;
    int m0 = blockIdx.x * 128;

    if (tid < 128) {
        s_src[tid] = ei[m0 + tid];
        s_dst[tid] = ei[EE + m0 + tid];
    }

    unsigned long long acc2[8][4];
#pragma unroll
    for (int i = 0; i < 8; i++)
#pragma unroll
        for (int j = 0; j < 4; j++) acc2[i][j] = 0ull;

    int lr = tid >> 3;
    int lc = (tid & 7) << 2;
    int wk = tid >> 3;
    int wc = (tid & 7) << 4;

    for (int k0 = 0; k0 < HID; k0 += 32) {
#pragma unroll
        for (int i = 0; i < 4; i++) {
            int m = m0 + lr + 32 * i;
            float4 v = *(const float4*)&g_e[(size_t)m * HID + k0 + lc];
            As[lc + 0][lr + 32 * i] = v.x;
            As[lc + 1][lr + 32 * i] = v.y;
            As[lc + 2][lr + 32 * i] = v.z;
            As[lc + 3][lr + 32 * i] = v.w;
        }
#pragma unroll
        for (int i = 0; i < 4; i++)
            *(float4*)&Ws[wk][wc + 4 * i] =
                *(const float4*)&W[(size_t)(k0 + wk) * HID + wc + 4 * i];
        __syncthreads();

#pragma unroll 8
        for (int kk = 0; kk < 32; kk++) {
            float4 a0 = *(const float4*)&As[kk][ty * 8];
            float4 a1 = *(const float4*)&As[kk][ty * 8 + 4];
            float4 b0 = *(const float4*)&Ws[kk][tx * 8];
            float4 b1 = *(const float4*)&Ws[kk][tx * 8 + 4];
            unsigned long long bp[4] = {pack2(b0.x, b0.y), pack2(b0.z, b0.w),
                                        pack2(b1.x, b1.y), pack2(b1.z, b1.w)};
            float a[8] = {a0.x, a0.y, a0.z, a0.w, a1.x, a1.y, a1.z, a1.w};
#pragma unroll
            for (int i = 0; i < 8; i++) {
                unsigned long long ap = bcast2(a[i]);
#pragma unroll
                for (int j = 0; j < 4; j++) ffma2(acc2[i][j], ap, bp[j]);
            }
        }
        __syncthreads();
    }

    // epilogue: per-row per-head attention score
    int c0 = tx * 8;                 // this thread's 8 columns, all in head tx/4
    float att_r[8];
#pragma unroll
    for (int j = 0; j < 8; j++) att_r[j] = __ldg(&att[c0 + j]);

#pragma unroll
    for (int i = 0; i < 8; i++) {
        int row = ty * 8 + i;
        int src = s_src[row];
        int dst = s_dst[row];
        float4 xl0 = *(const float4*)&g_xl[(size_t)src * HID + c0];
        float4 xl1 = *(const float4*)&g_xl[(size_t)src * HID + c0 + 4];
        float4 xr0 = *(const float4*)&g_xr[(size_t)dst * HID + c0];
        float4 xr1 = *(const float4*)&g_xr[(size_t)dst * HID + c0 + 4];
        float xlv[8] = {xl0.x, xl0.y, xl0.z, xl0.w, xl1.x, xl1.y, xl1.z, xl1.w};
        float xrv[8] = {xr0.x, xr0.y, xr0.z, xr0.w, xr1.x, xr1.y, xr1.z, xr1.w};
        float part = 0.f;
#pragma unroll
        for (int j = 0; j < 8; j++) {
            float2 p = *(float2*)&acc2[i][j >> 1];
            float eev = (j & 1) ? p.y : p.x;
            float mval = eev + xlv[j] + xrv[j];
            mval = (mval > 0.f) ? mval : 0.2f * mval;      // leaky_relu(0.2)
            part = fmaf(mval, att_r[j], part);
        }
        // reduce across the 4 tx lanes of the same head (lane bits 0-1)
        part += __shfl_xor_sync(0xffffffffu, part, 1);
        part += __shfl_xor_sync(0xffffffffu, part, 2);
        if ((tx & 3) == 0)
            g_score[(size_t)(m0 + row) * 4 + (tx >> 2)] = part;
    }
}

// ---------------- layer-0 node projection (K=12) ----------------
__global__ void node_proj12(const float* __restrict__ x,
                            const float* __restrict__ Wl, const float* __restrict__ bl,
                            const float* __restrict__ Wr, const float* __restrict__ br) {
    int idx = blockIdx.x * blockDim.x + threadIdx.x;    // N*128 threads
    int n = idx >> 7, j = idx & 127;
    float a = __ldg(&bl[j]);
    float b = __ldg(&br[j]);
#pragma unroll
    for (int k = 0; k < 12; k++) {
        float xv = __ldg(&x[n * 12 + k]);
        a = fmaf(xv, __ldg(&Wl[k * HID + j]), a);
        b = fmaf(xv, __ldg(&Wr[k * HID + j]), b);
    }
    g_xl[idx] = a;
    g_xr[idx] = b;
}

// ---------------- fused per-node: softmax + aggregate + bias + LN + SiLU (+res) ----
template <bool RES, bool LAST>
__global__ void node_fused_kernel(const int* __restrict__ ei,
                                  const float* __restrict__ gat_bias,
                                  const float* __restrict__ lng,
                                  const float* __restrict__ lnb,
                                  float* __restrict__ dout) {
    int n = blockIdx.x * 4 + (threadIdx.x >> 5);
    int lane = threadIdx.x & 31;
    if (n >= NN) return;
    int s0 = g_rowptr[n];
    int s1 = g_rowptr[n + 1];

    float mx = -3.4e38f;
    for (int p = s0 * 4 + lane; p < s1 * 4; p += 32) {
        int e = g_eids[p >> 2];
        mx = fmaxf(mx, g_score[(size_t)e * 4 + (p & 3)]);
    }
    mx = fmaxf(mx, __shfl_xor_sync(0xffffffffu, mx, 4));
    mx = fmaxf(mx, __shfl_xor_sync(0xffffffffu, mx, 8));
    mx = fmaxf(mx, __shfl_xor_sync(0xffffffffu, mx, 16));

    float den = 0.f;
    for (int p = s0 * 4 + lane; p < s1 * 4; p += 32) {
        int e = g_eids[p >> 2];
        den += expf(g_score[(size_t)e * 4 + (p & 3)] - mx);
    }
    den += __shfl_xor_sync(0xffffffffu, den, 4);
    den += __shfl_xor_sync(0xffffffffu, den, 8);
    den += __shfl_xor_sync(0xffffffffu, den, 16);
    float inv = 1.f / (den + 1e-16f);

    float acc0 = 0.f, acc1 = 0.f, acc2 = 0.f, acc3 = 0.f;
    for (int i = s0; i < s1; i++) {
        int e = g_eids[i];
        int src = ei[e];
        float a = 0.f;
        if (lane < 4) a = expf(g_score[(size_t)e * 4 + lane] - mx) * inv;
        float al0 = __shfl_sync(0xffffffffu, a, 0);
        float al1 = __shfl_sync(0xffffffffu, a, 1);
        float al2 = __shfl_sync(0xffffffffu, a, 2);
        float al3 = __shfl_sync(0xffffffffu, a, 3);
        const float* xl = &g_xl[(size_t)src * HID];
        acc0 = fmaf(xl[0 * DH + lane], al0, acc0);
        acc1 = fmaf(xl[1 * DH + lane], al1, acc1);
        acc2 = fmaf(xl[2 * DH + lane], al2, acc2);
        acc3 = fmaf(xl[3 * DH + lane], al3, acc3);
    }

    float v0 = acc0 + __ldg(&gat_bias[0 * DH + lane]);
    float v1 = acc1 + __ldg(&gat_bias[1 * DH + lane]);
    float v2 = acc2 + __ldg(&gat_bias[2 * DH + lane]);
    float v3 = acc3 + __ldg(&gat_bias[3 * DH + lane]);

    float sm = v0 + v1 + v2 + v3;
#pragma unroll
    for (int off = 16; off; off >>= 1) sm += __shfl_xor_sync(0xffffffffu, sm, off);
    float mean = sm * (1.f / 128.f);
    float d0 = v0 - mean, d1 = v1 - mean, d2 = v2 - mean, d3 = v3 - mean;
    float sq = d0 * d0 + d1 * d1 + d2 * d2 + d3 * d3;
#pragma unroll
    for (int off = 16; off; off >>= 1) sq += __shfl_xor_sync(0xffffffffu, sq, off);
    float rstd = rsqrtf(sq * (1.f / 128.f) + 1e-5f);

#pragma unroll
    for (int h = 0; h < 4; h++) {
        int j = h * DH + lane;
        float d = (h == 0 ? d0 : h == 1 ? d1 : h == 2 ? d2 : d3);
        float t = fmaf(d * rstd, __ldg(&lng[j]), __ldg(&lnb[j]));
        float sil = t / (1.f + expf(-t));
        float o = RES ? (g_h[n * HID + j] + sil) : sil;
        if (LAST) dout[n * HID + j] = o;
        else      g_h[n * HID + j] = o;
    }
}

// ---------------- launch ----------------
extern "C" void kernel_launch(void* const* d_in, const int* in_sizes, int n_in,
                              void* d_out, int out_size) {
    const float* x     = (const float*)d_in[0];
    const int*   ei    = (const int*)  d_in[1];
    const float* eattr = (const float*)d_in[2];
    const float* epw   = (const float*)d_in[3];
    const float* epb   = (const float*)d_in[4];
    const float* l0Wl  = (const float*)d_in[5];
    const float* l0bl  = (const float*)d_in[6];
    const float* l0Wr  = (const float*)d_in[7];
    const float* l0br  = (const float*)d_in[8];
    const float* l0We  = (const float*)d_in[9];
    const float* l0att = (const float*)d_in[10];
    const float* l0bias= (const float*)d_in[11];
    const float* Wl    = (const float*)d_in[12];
    const float* bl    = (const float*)d_in[13];
    const float* Wr    = (const float*)d_in[14];
    const float* br    = (const float*)d_in[15];
    const float* We    = (const float*)d_in[16];
    const float* att   = (const float*)d_in[17];
    const float* bias  = (const float*)d_in[18];
    const float* lng   = (const float*)d_in[19];
    const float* lnb   = (const float*)d_in[20];
    float* out = (float*)d_out;

    // edge features (shared by all layers)
    eproj_kernel<<<(EE * HID) / 256, 256>>>(eattr, epw, epb);

    // CSR by destination (shared by all layers)
    zero_kernel<<<(NN + 255) / 256, 256>>>();
    hist_kernel<<<(EE + 255) / 256, 256>>>(ei);
    deg_block_sum<<<NBLK, 1024>>>();
    bsum_scan<<<1, 128>>>();
    rowptr_kernel<<<NBLK, 1024>>>();
    scatter_kernel<<<(EE + 255) / 256, 256>>>(ei);

    // ---- layer 0 (12 -> 128, no residual) ----
    node_proj12<<<(NN * HID) / 256, 256>>>(x, l0Wl, l0bl, l0Wr, l0br);
    gemm_edge_score<<<EE / 128, 256>>>(l0We, l0att, ei);
    node_fused_kernel<false, false><<<NN / 4, 128>>>(ei, l0bias, lng, lnb, nullptr);

    // ---- layers 1..3 (residual) ----
    for (int i = 0; i < 3; i++) {
        gemm_node<1><<<(NN + 127) / 128, 256>>>(Wl + i * HID * HID, bl + i * HID, NN);
        gemm_node<2><<<(NN + 127) / 128, 256>>>(Wr + i * HID * HID, br + i * HID, NN);
        gemm_edge_score<<<EE / 128, 256>>>(We + i * HID * HID, att + i * HID, ei);
        if (i < 2)
            node_fused_kernel<true, false><<<NN / 4, 128>>>(
                ei, bias + i * HID, lng + (i + 1) * HID, lnb + (i + 1) * HID, nullptr);
        else
            node_fused_kernel<true, true><<<NN / 4, 128>>>(
                ei, bias + i * HID, lng + (i + 1) * HID, lnb + (i + 1) * HID, out);
    }
}

// round 3
// speedup vs baseline: 1.2829x; 1.1178x over previous
#include <cuda_runtime.h>
#include <math.h>

#define NN 100000
#define EE 800000
#define HID 128
#define NH 4
#define DH 32
#define NBLK ((NN + 1023) / 1024)   // 98

// ---------------- scratch (static device globals; no allocation) ----------------
__device__ float g_e [(size_t)EE * HID];
__device__ float g_xl[NN * HID];
__device__ float g_xr[NN * HID];
__device__ float g_h [NN * HID];
__device__ float g_score[EE * NH];
__device__ int   g_deg[NN];
__device__ int   g_cursor[NN];
__device__ int   g_rowptr[NN + 1];
__device__ int   g_eids[EE];
__device__ int   g_bsum[NBLK];
__device__ int   g_boff[NBLK];

// ---------------- packed fp32x2 helpers (sm_103a FFMA2 via PTX) ----------------
__device__ __forceinline__ unsigned long long pack2(float x, float y) {
    unsigned long long r;
    asm("mov.b64 %0, {%1, %2};" : "=l"(r) : "f"(x), "f"(y));
    return r;
}
__device__ __forceinline__ unsigned long long bcast2(float x) {
    unsigned long long r;
    asm("mov.b64 %0, {%1, %1};" : "=l"(r) : "f"(x));
    return r;
}
__device__ __forceinline__ void ffma2(unsigned long long& d,
                                      unsigned long long a, unsigned long long b) {
    asm("fma.rn.f32x2 %0, %1, %2, %0;" : "+l"(d) : "l"(a), "l"(b));
}

__device__ __forceinline__ float fast_silu(float z) {
    return __fdividef(z, 1.0f + __expf(-z));
}

// ---------------- edge feature projection: e = silu(attr @ Wp + bp) --------------
__global__ void eproj_kernel(const float* __restrict__ attr,
                             const float* __restrict__ W,
                             const float* __restrict__ b) {
    int idx = blockIdx.x * blockDim.x + threadIdx.x;   // E*32 threads
    int e = idx >> 5, c4 = (idx & 31) << 2;
    float a0 = __ldg(&attr[e * 3 + 0]);
    float a1 = __ldg(&attr[e * 3 + 1]);
    float a2 = __ldg(&attr[e * 3 + 2]);
    float4 o;
    float* op = &o.x;
#pragma unroll
    for (int u = 0; u < 4; u++) {
        int j = c4 + u;
        float z = __ldg(&b[j]);
        z = fmaf(a0, __ldg(&W[j]),           z);
        z = fmaf(a1, __ldg(&W[HID + j]),     z);
        z = fmaf(a2, __ldg(&W[2 * HID + j]), z);
        op[u] = fast_silu(z);
    }
    *(float4*)&g_e[(size_t)e * HID + c4] = o;
}

// ---------------- CSR build (by dst) ----------------
__global__ void zero_kernel() {
    int i = blockIdx.x * blockDim.x + threadIdx.x;
    if (i < NN) { g_deg[i] = 0; g_cursor[i] = 0; }
}

__global__ void hist_kernel(const int* __restrict__ ei) {
    int e = blockIdx.x * blockDim.x + threadIdx.x;
    if (e < EE) atomicAdd(&g_deg[ei[EE + e]], 1);
}

__global__ void deg_block_sum() {
    __shared__ int sh[1024];
    int i = blockIdx.x * 1024 + threadIdx.x;
    sh[threadIdx.x] = (i < NN) ? g_deg[i] : 0;
    __syncthreads();
    for (int off = 512; off; off >>= 1) {
        if (threadIdx.x < off) sh[threadIdx.x] += sh[threadIdx.x + off];
        __syncthreads();
    }
    if (threadIdx.x == 0) g_bsum[blockIdx.x] = sh[0];
}

__global__ void bsum_scan() {
    __shared__ int sh[128];
    int t = threadIdx.x;
    int v = (t < NBLK) ? g_bsum[t] : 0;
    sh[t] = v;
    __syncthreads();
    for (int off = 1; off < 128; off <<= 1) {
        int u = (t >= off) ? sh[t - off] : 0;
        __syncthreads();
        sh[t] += u;
        __syncthreads();
    }
    if (t < NBLK) g_boff[t] = sh[t] - v;
}

__global__ void rowptr_kernel() {
    __shared__ int sh[1024];
    int i = blockIdx.x * 1024 + threadIdx.x;
    int v = (i < NN) ? g_deg[i] : 0;
    sh[threadIdx.x] = v;
    __syncthreads();
    for (int off = 1; off < 1024; off <<= 1) {
        int u = (threadIdx.x >= off) ? sh[threadIdx.x - off] : 0;
        __syncthreads();
        sh[threadIdx.x] += u;
        __syncthreads();
    }
    if (i < NN) g_rowptr[i + 1] = sh[threadIdx.x] + g_boff[blockIdx.x];
    if (i == 0) g_rowptr[0] = 0;
}

__global__ void scatter_kernel(const int* __restrict__ ei) {
    int e = blockIdx.x * blockDim.x + threadIdx.x;
    if (e < EE) {
        int d = ei[EE + e];
        int pos = atomicAdd(&g_cursor[d], 1);
        g_eids[g_rowptr[d] + pos] = e;
    }
}

// ================= shared GEMM machinery (persistent W in smem) ==================
// smem layout: Wsm[128*128] floats, then As[32][132], then (edge only) src/dst[128]
#define WS_FLOATS (HID * HID)
#define AS_PAD 132
#define AS_FLOATS (32 * AS_PAD)

__device__ __forceinline__ void load_W_smem(float* Wsm, const float* __restrict__ W,
                                            int tid) {
    const float4* Wv = (const float4*)W;
    float4* Wd = (float4*)Wsm;
#pragma unroll
    for (int i = 0; i < WS_FLOATS / 4 / 256; i++)
        Wd[tid + 256 * i] = Wv[tid + 256 * i];
}

// prefetch one 128x32 A chunk into regs (guarded)
template <bool GUARD>
__device__ __forceinline__ void loadA_regs(float4 pa[4], const float* __restrict__ A,
                                           int m0, int k0, int lr, int lc, int M) {
#pragma unroll
    for (int i = 0; i < 4; i++) {
        int m = m0 + lr + 32 * i;
        if (!GUARD || m < M)
            pa[i] = *(const float4*)&A[(size_t)m * HID + k0 + lc];
        else
            pa[i] = make_float4(0.f, 0.f, 0.f, 0.f);
    }
}

__device__ __forceinline__ void storeA_smem(float* As, const float4 pa[4],
                                            int lr, int lc) {
#pragma unroll
    for (int i = 0; i < 4; i++) {
        As[(lc + 0) * AS_PAD + lr + 32 * i] = pa[i].x;
        As[(lc + 1) * AS_PAD + lr + 32 * i] = pa[i].y;
        As[(lc + 2) * AS_PAD + lr + 32 * i] = pa[i].z;
        As[(lc + 3) * AS_PAD + lr + 32 * i] = pa[i].w;
    }
}

__device__ __forceinline__ void compute_chunk(unsigned long long acc2[8][4],
                                              const float* As, const float* Wsm,
                                              int k0, int tx, int ty) {
#pragma unroll 8
    for (int kk = 0; kk < 32; kk++) {
        float4 a0 = *(const float4*)&As[kk * AS_PAD + ty * 8];
        float4 a1 = *(const float4*)&As[kk * AS_PAD + ty * 8 + 4];
        float4 b0 = *(const float4*)&Wsm[(k0 + kk) * HID + tx * 8];
        float4 b1 = *(const float4*)&Wsm[(k0 + kk) * HID + tx * 8 + 4];
        unsigned long long bp[4] = {pack2(b0.x, b0.y), pack2(b0.z, b0.w),
                                    pack2(b1.x, b1.y), pack2(b1.z, b1.w)};
        float a[8] = {a0.x, a0.y, a0.z, a0.w, a1.x, a1.y, a1.z, a1.w};
#pragma unroll
        for (int i = 0; i < 8; i++) {
            unsigned long long ap = bcast2(a[i]);
#pragma unroll
            for (int j = 0; j < 4; j++) ffma2(acc2[i][j], ap, bp[j]);
        }
    }
}

// ---------------- node GEMM: xl/xr = g_h @ W + bias (blockIdx.y picks) -----------
__global__ __launch_bounds__(256, 2) void gemm_node(const float* __restrict__ Wl,
                                                    const float* __restrict__ bl,
                                                    const float* __restrict__ Wr,
                                                    const float* __restrict__ br) {
    extern __shared__ __align__(16) float smem[];
    float* Wsm = smem;
    float* As = smem + WS_FLOATS;

    const float* W    = blockIdx.y ? Wr : Wl;
    const float* bias = blockIdx.y ? br : bl;
    float* C          = blockIdx.y ? g_xr : g_xl;
    const float* A = g_h;

    int tid = threadIdx.x;
    int tx = tid & 15, ty = tid >> 4;
    int lr = tid >> 3, lc = (tid & 7) << 2;
    int m0 = blockIdx.x * 128;

    load_W_smem(Wsm, W, tid);

    unsigned long long acc2[8][4];
#pragma unroll
    for (int i = 0; i < 8; i++)
#pragma unroll
        for (int j = 0; j < 4; j++) acc2[i][j] = 0ull;

    float4 pa[4];
    loadA_regs<true>(pa, A, m0, 0, lr, lc, NN);
    storeA_smem(As, pa, lr, lc);
    __syncthreads();

#pragma unroll
    for (int c = 0; c < 4; c++) {
        if (c < 3) loadA_regs<true>(pa, A, m0, (c + 1) * 32, lr, lc, NN);
        compute_chunk(acc2, As, Wsm, c * 32, tx, ty);
        __syncthreads();
        if (c < 3) { storeA_smem(As, pa, lr, lc); __syncthreads(); }
    }

#pragma unroll
    for (int i = 0; i < 8; i++) {
        int m = m0 + ty * 8 + i;
        if (m < NN) {
#pragma unroll
            for (int jp = 0; jp < 4; jp += 2) {
                float2 p0 = *(float2*)&acc2[i][jp];
                float2 p1 = *(float2*)&acc2[i][jp + 1];
                int ccol = tx * 8 + jp * 2;
                float4 o;
                o.x = p0.x + __ldg(&bias[ccol + 0]);
                o.y = p0.y + __ldg(&bias[ccol + 1]);
                o.z = p1.x + __ldg(&bias[ccol + 2]);
                o.w = p1.y + __ldg(&bias[ccol + 3]);
                *(float4*)&C[(size_t)m * HID + ccol] = o;
            }
        }
    }
}

// ---------------- fused edge GEMM + attention score ------------------------------
__global__ __launch_bounds__(256, 2) void gemm_edge_score(const float* __restrict__ W,
                                                          const float* __restrict__ att,
                                                          const int* __restrict__ ei) {
    extern __shared__ __align__(16) float smem[];
    float* Wsm = smem;
    float* As = smem + WS_FLOATS;
    int* s_src = (int*)(smem + WS_FLOATS + AS_FLOATS);
    int* s_dst = s_src + 128;

    int tid = threadIdx.x;
    int tx = tid & 15, ty = tid >> 4;
    int lr = tid >> 3, lc = (tid & 7) << 2;
    int m0 = blockIdx.x * 128;

    if (tid < 128) {
        s_src[tid] = ei[m0 + tid];
        s_dst[tid] = ei[EE + m0 + tid];
    }
    load_W_smem(Wsm, W, tid);

    unsigned long long acc2[8][4];
#pragma unroll
    for (int i = 0; i < 8; i++)
#pragma unroll
        for (int j = 0; j < 4; j++) acc2[i][j] = 0ull;

    float4 pa[4];
    loadA_regs<false>(pa, g_e, m0, 0, lr, lc, EE);
    storeA_smem(As, pa, lr, lc);
    __syncthreads();

#pragma unroll
    for (int c = 0; c < 4; c++) {
        if (c < 3) loadA_regs<false>(pa, g_e, m0, (c + 1) * 32, lr, lc, EE);
        compute_chunk(acc2, As, Wsm, c * 32, tx, ty);
        __syncthreads();
        if (c < 3) { storeA_smem(As, pa, lr, lc); __syncthreads(); }
    }

    // epilogue: per-row per-head attention score
    int c0 = tx * 8;
    float att_r[8];
#pragma unroll
    for (int j = 0; j < 8; j++) att_r[j] = __ldg(&att[c0 + j]);

#pragma unroll
    for (int i = 0; i < 8; i++) {
        int row = ty * 8 + i;
        int src = s_src[row];
        int dst = s_dst[row];
        float4 xl0 = *(const float4*)&g_xl[(size_t)src * HID + c0];
        float4 xl1 = *(const float4*)&g_xl[(size_t)src * HID + c0 + 4];
        float4 xr0 = *(const float4*)&g_xr[(size_t)dst * HID + c0];
        float4 xr1 = *(const float4*)&g_xr[(size_t)dst * HID + c0 + 4];
        float xlv[8] = {xl0.x, xl0.y, xl0.z, xl0.w, xl1.x, xl1.y, xl1.z, xl1.w};
        float xrv[8] = {xr0.x, xr0.y, xr0.z, xr0.w, xr1.x, xr1.y, xr1.z, xr1.w};
        float part = 0.f;
#pragma unroll
        for (int j = 0; j < 8; j++) {
            float2 p = *(float2*)&acc2[i][j >> 1];
            float eev = (j & 1) ? p.y : p.x;
            float mval = eev + xlv[j] + xrv[j];
            mval = (mval > 0.f) ? mval : 0.2f * mval;
            part = fmaf(mval, att_r[j], part);
        }
        part += __shfl_xor_sync(0xffffffffu, part, 1);
        part += __shfl_xor_sync(0xffffffffu, part, 2);
        if ((tx & 3) == 0)
            g_score[(size_t)(m0 + row) * 4 + (tx >> 2)] = part;
    }
}

// ---------------- layer-0 node projection (K=12) ----------------
__global__ void node_proj12(const float* __restrict__ x,
                            const float* __restrict__ Wl, const float* __restrict__ bl,
                            const float* __restrict__ Wr, const float* __restrict__ br) {
    int idx = blockIdx.x * blockDim.x + threadIdx.x;
    int n = idx >> 7, j = idx & 127;
    float a = __ldg(&bl[j]);
    float b = __ldg(&br[j]);
#pragma unroll
    for (int k = 0; k < 12; k++) {
        float xv = __ldg(&x[n * 12 + k]);
        a = fmaf(xv, __ldg(&Wl[k * HID + j]), a);
        b = fmaf(xv, __ldg(&Wr[k * HID + j]), b);
    }
    g_xl[idx] = a;
    g_xr[idx] = b;
}

// ---------------- fused per-node: softmax + aggregate + bias + LN + SiLU (+res) ---
template <bool RES, bool LAST>
__global__ void node_fused_kernel(const int* __restrict__ ei,
                                  const float* __restrict__ gat_bias,
                                  const float* __restrict__ lng,
                                  const float* __restrict__ lnb,
                                  float* __restrict__ dout) {
    int n = blockIdx.x * 4 + (threadIdx.x >> 5);
    int lane = threadIdx.x & 31;
    if (n >= NN) return;
    int s0 = g_rowptr[n];
    int s1 = g_rowptr[n + 1];

    float mx = -3.4e38f;
    for (int p = s0 * 4 + lane; p < s1 * 4; p += 32) {
        int e = g_eids[p >> 2];
        mx = fmaxf(mx, g_score[(size_t)e * 4 + (p & 3)]);
    }
    mx = fmaxf(mx, __shfl_xor_sync(0xffffffffu, mx, 4));
    mx = fmaxf(mx, __shfl_xor_sync(0xffffffffu, mx, 8));
    mx = fmaxf(mx, __shfl_xor_sync(0xffffffffu, mx, 16));

    float den = 0.f;
    for (int p = s0 * 4 + lane; p < s1 * 4; p += 32) {
        int e = g_eids[p >> 2];
        den += __expf(g_score[(size_t)e * 4 + (p & 3)] - mx);
    }
    den += __shfl_xor_sync(0xffffffffu, den, 4);
    den += __shfl_xor_sync(0xffffffffu, den, 8);
    den += __shfl_xor_sync(0xffffffffu, den, 16);
    float inv = __fdividef(1.f, den + 1e-16f);

    float acc0 = 0.f, acc1 = 0.f, acc2 = 0.f, acc3 = 0.f;
    for (int i = s0; i < s1; i++) {
        int e = g_eids[i];
        int src = ei[e];
        float a = 0.f;
        if (lane < 4) a = __expf(g_score[(size_t)e * 4 + lane] - mx) * inv;
        float al0 = __shfl_sync(0xffffffffu, a, 0);
        float al1 = __shfl_sync(0xffffffffu, a, 1);
        float al2 = __shfl_sync(0xffffffffu, a, 2);
        float al3 = __shfl_sync(0xffffffffu, a, 3);
        const float* xl = &g_xl[(size_t)src * HID];
        acc0 = fmaf(xl[0 * DH + lane], al0, acc0);
        acc1 = fmaf(xl[1 * DH + lane], al1, acc1);
        acc2 = fmaf(xl[2 * DH + lane], al2, acc2);
        acc3 = fmaf(xl[3 * DH + lane], al3, acc3);
    }

    float v0 = acc0 + __ldg(&gat_bias[0 * DH + lane]);
    float v1 = acc1 + __ldg(&gat_bias[1 * DH + lane]);
    float v2 = acc2 + __ldg(&gat_bias[2 * DH + lane]);
    float v3 = acc3 + __ldg(&gat_bias[3 * DH + lane]);

    float sm = v0 + v1 + v2 + v3;
#pragma unroll
    for (int off = 16; off; off >>= 1) sm += __shfl_xor_sync(0xffffffffu, sm, off);
    float mean = sm * (1.f / 128.f);
    float d0 = v0 - mean, d1 = v1 - mean, d2 = v2 - mean, d3 = v3 - mean;
    float sq = d0 * d0 + d1 * d1 + d2 * d2 + d3 * d3;
#pragma unroll
    for (int off = 16; off; off >>= 1) sq += __shfl_xor_sync(0xffffffffu, sq, off);
    float rstd = rsqrtf(sq * (1.f / 128.f) + 1e-5f);

#pragma unroll
    for (int h = 0; h < 4; h++) {
        int j = h * DH + lane;
        float d = (h == 0 ? d0 : h == 1 ? d1 : h == 2 ? d2 : d3);
        float t = fmaf(d * rstd, __ldg(&lng[j]), __ldg(&lnb[j]));
        float sil = fast_silu(t);
        float o = RES ? (g_h[n * HID + j] + sil) : sil;
        if (LAST) dout[n * HID + j] = o;
        else      g_h[n * HID + j] = o;
    }
}

// ---------------- launch ----------------
extern "C" void kernel_launch(void* const* d_in, const int* in_sizes, int n_in,
                              void* d_out, int out_size) {
    const float* x     = (const float*)d_in[0];
    const int*   ei    = (const int*)  d_in[1];
    const float* eattr = (const float*)d_in[2];
    const float* epw   = (const float*)d_in[3];
    const float* epb   = (const float*)d_in[4];
    const float* l0Wl  = (const float*)d_in[5];
    const float* l0bl  = (const float*)d_in[6];
    const float* l0Wr  = (const float*)d_in[7];
    const float* l0br  = (const float*)d_in[8];
    const float* l0We  = (const float*)d_in[9];
    const float* l0att = (const float*)d_in[10];
    const float* l0bias= (const float*)d_in[11];
    const float* Wl    = (const float*)d_in[12];
    const float* bl    = (const float*)d_in[13];
    const float* Wr    = (const float*)d_in[14];
    const float* br    = (const float*)d_in[15];
    const float* We    = (const float*)d_in[16];
    const float* att   = (const float*)d_in[17];
    const float* bias  = (const float*)d_in[18];
    const float* lng   = (const float*)d_in[19];
    const float* lnb   = (const float*)d_in[20];
    float* out = (float*)d_out;

    const int EDGE_SMEM = (WS_FLOATS + AS_FLOATS) * 4 + 2 * 128 * 4;
    const int NODE_SMEM = (WS_FLOATS + AS_FLOATS) * 4;
    static bool attr_set = false;
    if (!attr_set) {
        cudaFuncSetAttribute(gemm_edge_score,
                             cudaFuncAttributeMaxDynamicSharedMemorySize, EDGE_SMEM);
        cudaFuncSetAttribute(gemm_node,
                             cudaFuncAttributeMaxDynamicSharedMemorySize, NODE_SMEM);
        attr_set = true;
    }

    // 1..4: eproj, node_proj12, zero, edge-GEMM L0 (position 4 -> ncu capture)
    eproj_kernel<<<(EE * 32) / 256, 256>>>(eattr, epw, epb);
    node_proj12<<<(NN * HID) / 256, 256>>>(x, l0Wl, l0bl, l0Wr, l0br);
    zero_kernel<<<(NN + 255) / 256, 256>>>();
    gemm_edge_score<<<EE / 128, 256, EDGE_SMEM>>>(l0We, l0att, ei);

    // CSR build
    hist_kernel<<<(EE + 255) / 256, 256>>>(ei);
    deg_block_sum<<<NBLK, 1024>>>();
    bsum_scan<<<1, 128>>>();
    rowptr_kernel<<<NBLK, 1024>>>();
    scatter_kernel<<<(EE + 255) / 256, 256>>>(ei);

    node_fused_kernel<false, false><<<NN / 4, 128>>>(ei, l0bias, lng, lnb, nullptr);

    // layers 1..3 (residual)
    for (int i = 0; i < 3; i++) {
        dim3 ng((NN + 127) / 128, 2);
        gemm_node<<<ng, 256, NODE_SMEM>>>(Wl + i * HID * HID, bl + i * HID,
                                          Wr + i * HID * HID, br + i * HID);
        gemm_edge_score<<<EE / 128, 256, EDGE_SMEM>>>(We + i * HID * HID,
                                                      att + i * HID, ei);
        if (i < 2)
            node_fused_kernel<true, false><<<NN / 4, 128>>>(
                ei, bias + i * HID, lng + (i + 1) * HID, lnb + (i + 1) * HID, nullptr);
        else
            node_fused_kernel<true, true><<<NN / 4, 128>>>(
                ei, bias + i * HID, lng + (i + 1) * HID, lnb + (i + 1) * HID, out);
    }
}

// round 5
// speedup vs baseline: 1.6213x; 1.2637x over previous
#include <cuda_runtime.h>
#include <cuda_bf16.h>
#include <math.h>
#include <stdint.h>

#define NN 100000
#define EE 800000
#define HID 128
#define NH 4
#define DH 32
#define NBLK ((NN + 1023) / 1024)   // 98

// ---------------- scratch (static device globals; no allocation) ----------------
__device__ float g_e [(size_t)EE * HID];
__device__ float g_xl[NN * HID];
__device__ float g_xr[NN * HID];
__device__ float g_h [NN * HID];
__device__ float g_score[EE * NH];
__device__ unsigned int g_Whi[HID * HID / 2];   // W^T bf16-pair image (hi), [n][k/2]
__device__ unsigned int g_Wlo[HID * HID / 2];   // lo part
__device__ int   g_deg[NN];
__device__ int   g_cursor[NN];
__device__ int   g_rowptr[NN + 1];
__device__ int   g_eids[EE];
__device__ int   g_bsum[NBLK];
__device__ int   g_boff[NBLK];

// ---------------- packed fp32x2 helpers (FFMA2 via PTX) ----------------
__device__ __forceinline__ unsigned long long pack2(float x, float y) {
    unsigned long long r;
    asm("mov.b64 %0, {%1, %2};" : "=l"(r) : "f"(x), "f"(y));
    return r;
}
__device__ __forceinline__ unsigned long long bcast2(float x) {
    unsigned long long r;
    asm("mov.b64 %0, {%1, %1};" : "=l"(r) : "f"(x));
    return r;
}
__device__ __forceinline__ void ffma2(unsigned long long& d,
                                      unsigned long long a, unsigned long long b) {
    asm("fma.rn.f32x2 %0, %1, %2, %0;" : "+l"(d) : "l"(a), "l"(b));
}
__device__ __forceinline__ float fast_silu(float z) {
    return __fdividef(z, 1.0f + __expf(-z));
}

// bf16 pair pack + hi/lo split
__device__ __forceinline__ unsigned int packbf2(float x, float y) {
    __nv_bfloat162 t = __floats2bfloat162_rn(x, y);
    return *(unsigned int*)&t;
}
__device__ __forceinline__ void bf_split(float x, float& hi, float& lo) {
    __nv_bfloat16 h = __float2bfloat16_rn(x);
    hi = __bfloat162float(h);
    lo = x - hi;
}

// warp-level bf16 MMA: D(16x8,f32) += A(16x16,bf16 row) * B(16x8,bf16 col)
__device__ __forceinline__ void mma_bf16(float c[4],
                                         unsigned int a0, unsigned int a1,
                                         unsigned int a2, unsigned int a3,
                                         unsigned int b0, unsigned int b1) {
    asm volatile("mma.sync.aligned.m16n8k16.row.col.f32.bf16.bf16.f32 "
                 "{%0,%1,%2,%3}, {%4,%5,%6,%7}, {%8,%9}, {%0,%1,%2,%3};"
                 : "+f"(c[0]), "+f"(c[1]), "+f"(c[2]), "+f"(c[3])
                 : "r"(a0), "r"(a1), "r"(a2), "r"(a3), "r"(b0), "r"(b1));
}

// ---------------- edge feature projection ----------------
__global__ void eproj_kernel(const float* __restrict__ attr,
                             const float* __restrict__ W,
                             const float* __restrict__ b) {
    int idx = blockIdx.x * blockDim.x + threadIdx.x;   // E*32 threads
    int e = idx >> 5, c4 = (idx & 31) << 2;
    float a0 = __ldg(&attr[e * 3 + 0]);
    float a1 = __ldg(&attr[e * 3 + 1]);
    float a2 = __ldg(&attr[e * 3 + 2]);
    float4 o;
    float* op = &o.x;
#pragma unroll
    for (int u = 0; u < 4; u++) {
        int j = c4 + u;
        float z = __ldg(&b[j]);
        z = fmaf(a0, __ldg(&W[j]),           z);
        z = fmaf(a1, __ldg(&W[HID + j]),     z);
        z = fmaf(a2, __ldg(&W[2 * HID + j]), z);
        op[u] = fast_silu(z);
    }
    *(float4*)&g_e[(size_t)e * HID + c4] = o;
}

// ---------------- CSR build (by dst) ----------------
__global__ void zero_kernel() {
    int i = blockIdx.x * blockDim.x + threadIdx.x;
    if (i < NN) { g_deg[i] = 0; g_cursor[i] = 0; }
}
__global__ void hist_kernel(const int* __restrict__ ei) {
    int e = blockIdx.x * blockDim.x + threadIdx.x;
    if (e < EE) atomicAdd(&g_deg[ei[EE + e]], 1);
}
__global__ void deg_block_sum() {
    __shared__ int sh[1024];
    int i = blockIdx.x * 1024 + threadIdx.x;
    sh[threadIdx.x] = (i < NN) ? g_deg[i] : 0;
    __syncthreads();
    for (int off = 512; off; off >>= 1) {
        if (threadIdx.x < off) sh[threadIdx.x] += sh[threadIdx.x + off];
        __syncthreads();
    }
    if (threadIdx.x == 0) g_bsum[blockIdx.x] = sh[0];
}
__global__ void bsum_scan() {
    __shared__ int sh[128];
    int t = threadIdx.x;
    int v = (t < NBLK) ? g_bsum[t] : 0;
    sh[t] = v;
    __syncthreads();
    for (int off = 1; off < 128; off <<= 1) {
        int u = (t >= off) ? sh[t - off] : 0;
        __syncthreads();
        sh[t] += u;
        __syncthreads();
    }
    if (t < NBLK) g_boff[t] = sh[t] - v;
}
__global__ void rowptr_kernel() {
    __shared__ int sh[1024];
    int i = blockIdx.x * 1024 + threadIdx.x;
    int v = (i < NN) ? g_deg[i] : 0;
    sh[threadIdx.x] = v;
    __syncthreads();
    for (int off = 1; off < 1024; off <<= 1) {
        int u = (threadIdx.x >= off) ? sh[threadIdx.x - off] : 0;
        __syncthreads();
        sh[threadIdx.x] += u;
        __syncthreads();
    }
    if (i < NN) g_rowptr[i + 1] = sh[threadIdx.x] + g_boff[blockIdx.x];
    if (i == 0) g_rowptr[0] = 0;
}
__global__ void scatter_kernel(const int* __restrict__ ei) {
    int e = blockIdx.x * blockDim.x + threadIdx.x;
    if (e < EE) {
        int d = ei[EE + e];
        int pos = atomicAdd(&g_cursor[d], 1);
        g_eids[g_rowptr[d] + pos] = e;
    }
}

// ================= SIMT GEMM machinery (node projections) ==================
#define WS_FLOATS (HID * HID)
#define AS_PAD 132
#define AS_FLOATS (32 * AS_PAD)

__device__ __forceinline__ void load_W_smem(float* Wsm, const float* __restrict__ W, int tid) {
    const float4* Wv = (const float4*)W;
    float4* Wd = (float4*)Wsm;
#pragma unroll
    for (int i = 0; i < WS_FLOATS / 4 / 256; i++)
        Wd[tid + 256 * i] = Wv[tid + 256 * i];
}
template <bool GUARD>
__device__ __forceinline__ void loadA_regs(float4 pa[4], const float* __restrict__ A,
                                           int m0, int k0, int lr, int lc, int M) {
#pragma unroll
    for (int i = 0; i < 4; i++) {
        int m = m0 + lr + 32 * i;
        if (!GUARD || m < M)
            pa[i] = *(const float4*)&A[(size_t)m * HID + k0 + lc];
        else
            pa[i] = make_float4(0.f, 0.f, 0.f, 0.f);
    }
}
__device__ __forceinline__ void storeA_smem(float* As, const float4 pa[4], int lr, int lc) {
#pragma unroll
    for (int i = 0; i < 4; i++) {
        As[(lc + 0) * AS_PAD + lr + 32 * i] = pa[i].x;
        As[(lc + 1) * AS_PAD + lr + 32 * i] = pa[i].y;
        As[(lc + 2) * AS_PAD + lr + 32 * i] = pa[i].z;
        As[(lc + 3) * AS_PAD + lr + 32 * i] = pa[i].w;
    }
}
__device__ __forceinline__ void compute_chunk(unsigned long long acc2[8][4],
                                              const float* As, const float* Wsm,
                                              int k0, int tx, int ty) {
#pragma unroll 8
    for (int kk = 0; kk < 32; kk++) {
        float4 a0 = *(const float4*)&As[kk * AS_PAD + ty * 8];
        float4 a1 = *(const float4*)&As[kk * AS_PAD + ty * 8 + 4];
        float4 b0 = *(const float4*)&Wsm[(k0 + kk) * HID + tx * 8];
        float4 b1 = *(const float4*)&Wsm[(k0 + kk) * HID + tx * 8 + 4];
        unsigned long long bp[4] = {pack2(b0.x, b0.y), pack2(b0.z, b0.w),
                                    pack2(b1.x, b1.y), pack2(b1.z, b1.w)};
        float a[8] = {a0.x, a0.y, a0.z, a0.w, a1.x, a1.y, a1.z, a1.w};
#pragma unroll
        for (int i = 0; i < 8; i++) {
            unsigned long long ap = bcast2(a[i]);
#pragma unroll
            for (int j = 0; j < 4; j++) ffma2(acc2[i][j], ap, bp[j]);
        }
    }
}

__global__ __launch_bounds__(256, 2) void gemm_node(const float* __restrict__ Wl,
                                                    const float* __restrict__ bl,
                                                    const float* __restrict__ Wr,
                                                    const float* __restrict__ br) {
    extern __shared__ __align__(16) float smem[];
    float* Wsm = smem;
    float* As = smem + WS_FLOATS;

    const float* W    = blockIdx.y ? Wr : Wl;
    const float* bias = blockIdx.y ? br : bl;
    float* C          = blockIdx.y ? g_xr : g_xl;
    const float* A = g_h;

    int tid = threadIdx.x;
    int tx = tid & 15, ty = tid >> 4;
    int lr = tid >> 3, lc = (tid & 7) << 2;
    int m0 = blockIdx.x * 128;

    load_W_smem(Wsm, W, tid);

    unsigned long long acc2[8][4];
#pragma unroll
    for (int i = 0; i < 8; i++)
#pragma unroll
        for (int j = 0; j < 4; j++) acc2[i][j] = 0ull;

    float4 pa[4];
    loadA_regs<true>(pa, A, m0, 0, lr, lc, NN);
    storeA_smem(As, pa, lr, lc);
    __syncthreads();

#pragma unroll
    for (int c = 0; c < 4; c++) {
        if (c < 3) loadA_regs<true>(pa, A, m0, (c + 1) * 32, lr, lc, NN);
        compute_chunk(acc2, As, Wsm, c * 32, tx, ty);
        __syncthreads();
        if (c < 3) { storeA_smem(As, pa, lr, lc); __syncthreads(); }
    }

#pragma unroll
    for (int i = 0; i < 8; i++) {
        int m = m0 + ty * 8 + i;
        if (m < NN) {
#pragma unroll
            for (int jp = 0; jp < 4; jp += 2) {
                float2 p0 = *(float2*)&acc2[i][jp];
                float2 p1 = *(float2*)&acc2[i][jp + 1];
                int ccol = tx * 8 + jp * 2;
                float4 o;
                o.x = p0.x + __ldg(&bias[ccol + 0]);
                o.y = p0.y + __ldg(&bias[ccol + 1]);
                o.z = p1.x + __ldg(&bias[ccol + 2]);
                o.w = p1.y + __ldg(&bias[ccol + 3]);
                *(float4*)&C[(size_t)m * HID + ccol] = o;
            }
        }
    }
}

// ================= mma.sync bf16x3 edge GEMM + fused score =================
// W image prep: Wt[n][k] bf16 pairs, hi/lo split. idx = n*64 + kw (kw = k/2).
__global__ void wprep_kernel(const float* __restrict__ W) {
    int idx = blockIdx.x * 256 + threadIdx.x;   // 8192
    int n = idx >> 6, kw = idx & 63;
    float w0 = __ldg(&W[(2 * kw) * HID + n]);
    float w1 = __ldg(&W[(2 * kw + 1) * HID + n]);
    float h0, l0, h1, l1;
    bf_split(w0, h0, l0);
    bf_split(w1, h1, l1);
    g_Whi[idx] = packbf2(h0, h1);
    g_Wlo[idx] = packbf2(l0, l1);
}

// smem (words of 4B): Ahi[128*68], Alo, Bhi, Blo, then src/dst
#define EPAD 68
#define TILE_W (128 * EPAD)
#define ESM_WORDS (4 * TILE_W + 256)
#define ESM_BYTES (ESM_WORDS * 4)

__global__ __launch_bounds__(256, 1) void gemm_edge_score_mma(
        const float* __restrict__ att, const int* __restrict__ ei) {
    extern __shared__ __align__(16) unsigned int esm[];
    unsigned int* Ahi = esm;
    unsigned int* Alo = Ahi + TILE_W;
    unsigned int* Bhi = Alo + TILE_W;
    unsigned int* Blo = Bhi + TILE_W;
    int* s_src = (int*)(Blo + TILE_W);
    int* s_dst = s_src + 128;

    int tid = threadIdx.x;
    int m0 = blockIdx.x * 128;

    if (tid < 128) {
        s_src[tid] = ei[m0 + tid];
        s_dst[tid] = ei[EE + m0 + tid];
    }

    // stage W hi/lo: 128 n-rows x 64 words; uint4 copies
#pragma unroll
    for (int i = 0; i < 8; i++) {
        int idx = i * 256 + tid;          // 2048 uint4 = 8192 words
        int n = idx >> 4, kw4 = (idx & 15) << 2;
        uint4 vh = ((const uint4*)g_Whi)[idx];
        uint4 vl = ((const uint4*)g_Wlo)[idx];
        *(uint4*)&Bhi[n * EPAD + kw4] = vh;
        *(uint4*)&Blo[n * EPAD + kw4] = vl;
    }
    // stage A: 128 rows x 128 k; split to bf16 hi/lo
#pragma unroll
    for (int it = 0; it < 16; it++) {
        int idx = it * 256 + tid;         // 4096 float4 chunks
        int row = idx >> 5, k4 = (idx & 31) << 2;
        float4 v = *(const float4*)&g_e[(size_t)(m0 + row) * HID + k4];
        float hx, lx, hy, ly, hz, lz, hw, lw;
        bf_split(v.x, hx, lx); bf_split(v.y, hy, ly);
        bf_split(v.z, hz, lz); bf_split(v.w, hw, lw);
        uint2 ph = make_uint2(packbf2(hx, hy), packbf2(hz, hw));
        uint2 pl = make_uint2(packbf2(lx, ly), packbf2(lz, lw));
        *(uint2*)&Ahi[row * EPAD + (k4 >> 1)] = ph;
        *(uint2*)&Alo[row * EPAD + (k4 >> 1)] = pl;
    }
    __syncthreads();

    int wid = tid >> 5, lane = tid & 31;
    int g = lane >> 2, q = lane & 3;
    int mb = (wid & 3) * 32;      // warp rows mb..mb+31
    int nb = (wid >> 2) * 64;     // warp cols nb..nb+63

    float acc[2][8][4];
#pragma unroll
    for (int t = 0; t < 2; t++)
#pragma unroll
        for (int j = 0; j < 8; j++)
#pragma unroll
            for (int c = 0; c < 4; c++) acc[t][j][c] = 0.f;

    // 3 passes: (Ahi,Bhi), (Ahi,Blo), (Alo,Bhi) — all accumulate into acc
    for (int pass = 0; pass < 3; pass++) {
        const unsigned int* As = (pass == 2) ? Alo : Ahi;
        const unsigned int* Bs = (pass == 1) ? Blo : Bhi;
#pragma unroll
        for (int ks = 0; ks < 8; ks++) {
            int kw0 = ks * 8 + q;
            unsigned int a[2][4];
#pragma unroll
            for (int t = 0; t < 2; t++) {
                int r = mb + 16 * t + g;
                a[t][0] = As[r * EPAD + kw0];
                a[t][1] = As[(r + 8) * EPAD + kw0];
                a[t][2] = As[r * EPAD + kw0 + 4];
                a[t][3] = As[(r + 8) * EPAD + kw0 + 4];
            }
            unsigned int b[8][2];
#pragma unroll
            for (int j = 0; j < 8; j++) {
                int n = nb + 8 * j + g;
                b[j][0] = Bs[n * EPAD + kw0];
                b[j][1] = Bs[n * EPAD + kw0 + 4];
            }
#pragma unroll
            for (int t = 0; t < 2; t++)
#pragma unroll
                for (int j = 0; j < 8; j++)
                    mma_bf16(acc[t][j], a[t][0], a[t][1], a[t][2], a[t][3],
                             b[j][0], b[j][1]);
        }
    }

    // epilogue: score[e][h] = sum_d leaky(ee + xl[src] + xr[dst]) * att
    float2 attv[8];
#pragma unroll
    for (int j = 0; j < 8; j++)
        attv[j] = *(const float2*)&att[nb + 8 * j + 2 * q];

#pragma unroll
    for (int t = 0; t < 2; t++) {
#pragma unroll
        for (int rr = 0; rr < 2; rr++) {
            int row = mb + 16 * t + 8 * rr + g;
            int edge = m0 + row;
            int src = s_src[row], dst = s_dst[row];
            const float* xlp = &g_xl[(size_t)src * HID];
            const float* xrp = &g_xr[(size_t)dst * HID];
            float p0 = 0.f, p1 = 0.f;
#pragma unroll
            for (int j = 0; j < 8; j++) {
                int cc = nb + 8 * j + 2 * q;
                float2 xl = *(const float2*)&xlp[cc];
                float2 xr = *(const float2*)&xrp[cc];
                float e0 = acc[t][j][rr * 2 + 0] + xl.x + xr.x;
                float e1 = acc[t][j][rr * 2 + 1] + xl.y + xr.y;
                e0 = (e0 > 0.f) ? e0 : 0.2f * e0;
                e1 = (e1 > 0.f) ? e1 : 0.2f * e1;
                float ps = fmaf(e0, attv[j].x, e1 * attv[j].y);
                if (j < 4) p0 += ps; else p1 += ps;
            }
            p0 += __shfl_xor_sync(0xffffffffu, p0, 1);
            p0 += __shfl_xor_sync(0xffffffffu, p0, 2);
            p1 += __shfl_xor_sync(0xffffffffu, p1, 1);
            p1 += __shfl_xor_sync(0xffffffffu, p1, 2);
            if (q == 0)
                *(float2*)&g_score[(size_t)edge * 4 + (nb >> 5)] = make_float2(p0, p1);
        }
    }
}

// ---------------- layer-0 node projection (K=12) ----------------
__global__ void node_proj12(const float* __restrict__ x,
                            const float* __restrict__ Wl, const float* __restrict__ bl,
                            const float* __restrict__ Wr, const float* __restrict__ br) {
    int idx = blockIdx.x * blockDim.x + threadIdx.x;
    int n = idx >> 7, j = idx & 127;
    float a = __ldg(&bl[j]);
    float b = __ldg(&br[j]);
#pragma unroll
    for (int k = 0; k < 12; k++) {
        float xv = __ldg(&x[n * 12 + k]);
        a = fmaf(xv, __ldg(&Wl[k * HID + j]), a);
        b = fmaf(xv, __ldg(&Wr[k * HID + j]), b);
    }
    g_xl[idx] = a;
    g_xr[idx] = b;
}

// ---------------- fused per-node: softmax + aggregate + bias + LN + SiLU (+res) ---
template <bool RES, bool LAST>
__global__ void node_fused_kernel(const int* __restrict__ ei,
                                  const float* __restrict__ gat_bias,
                                  const float* __restrict__ lng,
                                  const float* __restrict__ lnb,
                                  float* __restrict__ dout) {
    int n = blockIdx.x * 4 + (threadIdx.x >> 5);
    int lane = threadIdx.x & 31;
    if (n >= NN) return;
    int s0 = g_rowptr[n];
    int s1 = g_rowptr[n + 1];

    float mx = -3.4e38f;
    for (int p = s0 * 4 + lane; p < s1 * 4; p += 32) {
        int e = g_eids[p >> 2];
        mx = fmaxf(mx, g_score[(size_t)e * 4 + (p & 3)]);
    }
    mx = fmaxf(mx, __shfl_xor_sync(0xffffffffu, mx, 4));
    mx = fmaxf(mx, __shfl_xor_sync(0xffffffffu, mx, 8));
    mx = fmaxf(mx, __shfl_xor_sync(0xffffffffu, mx, 16));

    float den = 0.f;
    for (int p = s0 * 4 + lane; p < s1 * 4; p += 32) {
        int e = g_eids[p >> 2];
        den += __expf(g_score[(size_t)e * 4 + (p & 3)] - mx);
    }
    den += __shfl_xor_sync(0xffffffffu, den, 4);
    den += __shfl_xor_sync(0xffffffffu, den, 8);
    den += __shfl_xor_sync(0xffffffffu, den, 16);
    float inv = __fdividef(1.f, den + 1e-16f);

    float acc0 = 0.f, acc1 = 0.f, acc2 = 0.f, acc3 = 0.f;
    for (int i = s0; i < s1; i++) {
        int e = g_eids[i];
        int src = ei[e];
        float a = 0.f;
        if (lane < 4) a = __expf(g_score[(size_t)e * 4 + lane] - mx) * inv;
        float al0 = __shfl_sync(0xffffffffu, a, 0);
        float al1 = __shfl_sync(0xffffffffu, a, 1);
        float al2 = __shfl_sync(0xffffffffu, a, 2);
        float al3 = __shfl_sync(0xffffffffu, a, 3);
        const float* xl = &g_xl[(size_t)src * HID];
        acc0 = fmaf(xl[0 * DH + lane], al0, acc0);
        acc1 = fmaf(xl[1 * DH + lane], al1, acc1);
        acc2 = fmaf(xl[2 * DH + lane], al2, acc2);
        acc3 = fmaf(xl[3 * DH + lane], al3, acc3);
    }

    float v0 = acc0 + __ldg(&gat_bias[0 * DH + lane]);
    float v1 = acc1 + __ldg(&gat_bias[1 * DH + lane]);
    float v2 = acc2 + __ldg(&gat_bias[2 * DH + lane]);
    float v3 = acc3 + __ldg(&gat_bias[3 * DH + lane]);

    float sm = v0 + v1 + v2 + v3;
#pragma unroll
    for (int off = 16; off; off >>= 1) sm += __shfl_xor_sync(0xffffffffu, sm, off);
    float mean = sm * (1.f / 128.f);
    float d0 = v0 - mean, d1 = v1 - mean, d2 = v2 - mean, d3 = v3 - mean;
    float sq = d0 * d0 + d1 * d1 + d2 * d2 + d3 * d3;
#pragma unroll
    for (int off = 16; off; off >>= 1) sq += __shfl_xor_sync(0xffffffffu, sq, off);
    float rstd = rsqrtf(sq * (1.f / 128.f) + 1e-5f);

#pragma unroll
    for (int h = 0; h < 4; h++) {
        int j = h * DH + lane;
        float d = (h == 0 ? d0 : h == 1 ? d1 : h == 2 ? d2 : d3);
        float t = fmaf(d * rstd, __ldg(&lng[j]), __ldg(&lnb[j]));
        float sil = fast_silu(t);
        float o = RES ? (g_h[n * HID + j] + sil) : sil;
        if (LAST) dout[n * HID + j] = o;
        else      g_h[n * HID + j] = o;
    }
}

// ---------------- launch ----------------
extern "C" void kernel_launch(void* const* d_in, const int* in_sizes, int n_in,
                              void* d_out, int out_size) {
    const float* x     = (const float*)d_in[0];
    const int*   ei    = (const int*)  d_in[1];
    const float* eattr = (const float*)d_in[2];
    const float* epw   = (const float*)d_in[3];
    const float* epb   = (const float*)d_in[4];
    const float* l0Wl  = (const float*)d_in[5];
    const float* l0bl  = (const float*)d_in[6];
    const float* l0Wr  = (const float*)d_in[7];
    const float* l0br  = (const float*)d_in[8];
    const float* l0We  = (const float*)d_in[9];
    const float* l0att = (const float*)d_in[10];
    const float* l0bias= (const float*)d_in[11];
    const float* Wl    = (const float*)d_in[12];
    const float* bl    = (const float*)d_in[13];
    const float* Wr    = (const float*)d_in[14];
    const float* br    = (const float*)d_in[15];
    const float* We    = (const float*)d_in[16];
    const float* att   = (const float*)d_in[17];
    const float* bias  = (const float*)d_in[18];
    const float* lng   = (const float*)d_in[19];
    const float* lnb   = (const float*)d_in[20];
    float* out = (float*)d_out;

    const int NODE_SMEM = (WS_FLOATS + AS_FLOATS) * 4;
    static bool attr_set = false;
    if (!attr_set) {
        cudaFuncSetAttribute(gemm_edge_score_mma,
                             cudaFuncAttributeMaxDynamicSharedMemorySize, ESM_BYTES);
        cudaFuncSetAttribute(gemm_node,
                             cudaFuncAttributeMaxDynamicSharedMemorySize, NODE_SMEM);
        attr_set = true;
    }

    // layer-0 prerequisites; edge GEMM kept at 4th launch for ncu capture
    eproj_kernel<<<(EE * 32) / 256, 256>>>(eattr, epw, epb);
    node_proj12<<<(NN * HID) / 256, 256>>>(x, l0Wl, l0bl, l0Wr, l0br);
    wprep_kernel<<<32, 256>>>(l0We);
    gemm_edge_score_mma<<<EE / 128, 256, ESM_BYTES>>>(l0att, ei);

    // CSR build
    zero_kernel<<<(NN + 255) / 256, 256>>>();
    hist_kernel<<<(EE + 255) / 256, 256>>>(ei);
    deg_block_sum<<<NBLK, 1024>>>();
    bsum_scan<<<1, 128>>>();
    rowptr_kernel<<<NBLK, 1024>>>();
    scatter_kernel<<<(EE + 255) / 256, 256>>>(ei);

    node_fused_kernel<false, false><<<NN / 4, 128>>>(ei, l0bias, lng, lnb, nullptr);

    // layers 1..3 (residual)
    for (int i = 0; i < 3; i++) {
        dim3 ng((NN + 127) / 128, 2);
        gemm_node<<<ng, 256, NODE_SMEM>>>(Wl + i * HID * HID, bl + i * HID,
                                          Wr + i * HID * HID, br + i * HID);
        wprep_kernel<<<32, 256>>>(We + i * HID * HID);
        gemm_edge_score_mma<<<EE / 128, 256, ESM_BYTES>>>(att + i * HID, ei);
        if (i < 2)
            node_fused_kernel<true, false><<<NN / 4, 128>>>(
                ei, bias + i * HID, lng + (i + 1) * HID, lnb + (i + 1) * HID, nullptr);
        else
            node_fused_kernel<true, true><<<NN / 4, 128>>>(
                ei, bias + i * HID, lng + (i + 1) * HID, lnb + (i + 1) * HID, out);
    }
}